// round 7
// baseline (speedup 1.0000x reference)
#include <cuda_runtime.h>
#include <cuda_bf16.h>

// Problem constants (fixed shapes per reference)
#define NN 100000
#define EE 600000
#define HH 128
#define GG 4000
#define TT 128

// Scratch (allocation-free: device globals)
__device__ float g_deg[NN];                 // degree, then dinv in-place
__device__ float g_h[(size_t)NN * HH];
__device__ float g_t[(size_t)NN * HH];
__device__ float g_o[(size_t)NN * HH];
__device__ float g_pool[(size_t)GG * HH];
__device__ float g_cnt[GG];

__constant__ int c_off[9] = {0, 119, 124, 136, 148, 158, 164, 170, 172};

// ---------------------------------------------------------------------------
__global__ void deg_init_kernel() {
    int i = blockIdx.x * blockDim.x + threadIdx.x;
    if (i < NN) g_deg[i] = 1.0f;
}

__global__ void deg_scatter_kernel(const int* __restrict__ dst) {
    int e = blockIdx.x * blockDim.x + threadIdx.x;
    if (e < EE) atomicAdd(&g_deg[dst[e]], 1.0f);
}

// AtomEncoder: h[n] = sum_f emb[x[n,f]+off[f]]; also deg -> dinv in place.
__global__ void embed_kernel(const int* __restrict__ x, const float* __restrict__ emb) {
    int n = blockIdx.x;
    int t = threadIdx.x;
    __shared__ int xi[9];
    if (t < 9) xi[t] = x[n * 9 + t] + c_off[t];
    __syncthreads();
    float v = 0.0f;
#pragma unroll
    for (int f = 0; f < 9; f++) v += emb[(size_t)xi[f] * HH + t];
    g_h[(size_t)n * HH + t] = v;
    if (t == 0) g_deg[n] = rsqrtf(g_deg[n]);
}

// ---------------------------------------------------------------------------
// GEMM: C[M,128] = A'[M,128] @ B[128,128]
// MODE 0: layer, A as-is.  MODE 1: layer, relu(A).  MODE 2: final, A/max(cnt,1).
// Layer epilogue: T = A'@B ; OUT = dinv^2 * T + bias   (self-loop init)
// Final epilogue: OUT = A'@B + bias
template <int MODE>
__global__ void gemm_kernel(const float* __restrict__ A, const float* __restrict__ B,
                            const float* __restrict__ bias, float* __restrict__ T,
                            float* __restrict__ OUT, int M) {
    __shared__ float As[8][128];
    __shared__ float Bs[8][128];
    const int tid = threadIdx.x;            // 256 threads
    const int row0 = blockIdx.x * 128;
    const int tx = tid & 15;                // 16 cols of threads
    const int ty = tid >> 4;                // 16 rows of threads
    const int arow = tid >> 1;              // A load: 128 rows x 2 float4
    const int acol = (tid & 1) << 2;
    const int brow = tid >> 5;              // B load: 8 rows x 32 float4
    const int bcol = (tid & 31) << 2;

    float acc[8][8];
#pragma unroll
    for (int i = 0; i < 8; i++)
#pragma unroll
        for (int j = 0; j < 8; j++) acc[i][j] = 0.0f;

    const int gr = row0 + arow;
    float prescale = 1.0f;
    if (MODE == 2) prescale = (gr < M) ? 1.0f / fmaxf(g_cnt[gr], 1.0f) : 0.0f;

    for (int k0 = 0; k0 < 128; k0 += 8) {
        float4 a4 = make_float4(0.f, 0.f, 0.f, 0.f);
        if (gr < M) a4 = *(const float4*)(A + (size_t)gr * HH + k0 + acol);
        if (MODE == 1) {
            a4.x = fmaxf(a4.x, 0.f); a4.y = fmaxf(a4.y, 0.f);
            a4.z = fmaxf(a4.z, 0.f); a4.w = fmaxf(a4.w, 0.f);
        }
        if (MODE == 2) { a4.x *= prescale; a4.y *= prescale; a4.z *= prescale; a4.w *= prescale; }
        As[acol + 0][arow] = a4.x;
        As[acol + 1][arow] = a4.y;
        As[acol + 2][arow] = a4.z;
        As[acol + 3][arow] = a4.w;
        *(float4*)&Bs[brow][bcol] = *(const float4*)(B + (size_t)(k0 + brow) * HH + bcol);
        __syncthreads();
#pragma unroll
        for (int k = 0; k < 8; k++) {
            float a[8], b[8];
#pragma unroll
            for (int i = 0; i < 8; i++) a[i] = As[k][(ty << 3) + i];
#pragma unroll
            for (int j = 0; j < 8; j++) b[j] = Bs[k][(tx << 3) + j];
#pragma unroll
            for (int i = 0; i < 8; i++)
#pragma unroll
                for (int j = 0; j < 8; j++) acc[i][j] += a[i] * b[j];
        }
        __syncthreads();
    }

#pragma unroll
    for (int i = 0; i < 8; i++) {
        const int r = row0 + (ty << 3) + i;
        if (r >= M) continue;
        if (MODE == 2) {
#pragma unroll
            for (int j = 0; j < 8; j++) {
                const int c = (tx << 3) + j;
                OUT[(size_t)r * TT + c] = acc[i][j] + bias[c];
            }
        } else {
            const float d = g_deg[r];   // dinv
            const float d2 = d * d;
#pragma unroll
            for (int j = 0; j < 8; j++) {
                const int c = (tx << 3) + j;
                const float v = acc[i][j];
                T[(size_t)r * HH + c] = v;
                OUT[(size_t)r * HH + c] = d2 * v + bias[c];
            }
        }
    }
}

// ---------------------------------------------------------------------------
// Edge scatter: out[dst] += t[src] * dinv[src] * dinv[dst]   (one warp / edge)
__global__ void edge_kernel(const int* __restrict__ src, const int* __restrict__ dst,
                            const float* __restrict__ t, float* __restrict__ out) {
    const int w = (blockIdx.x * blockDim.x + threadIdx.x) >> 5;
    const int lane = threadIdx.x & 31;
    if (w >= EE) return;
    const int s = src[w];
    const int d = dst[w];
    const float c = g_deg[s] * g_deg[d];
    float4 v = *(const float4*)(t + (size_t)s * HH + (lane << 2));
    v.x *= c; v.y *= c; v.z *= c; v.w *= c;
    float* p = out + (size_t)d * HH + (lane << 2);
    asm volatile("red.global.add.v4.f32 [%0], {%1,%2,%3,%4};"
                 :: "l"(p), "f"(v.x), "f"(v.y), "f"(v.z), "f"(v.w)
                 : "memory");
}

// ---------------------------------------------------------------------------
__global__ void pool_zero_kernel() {
    int i = blockIdx.x * blockDim.x + threadIdx.x;
    if (i < GG * HH) g_pool[i] = 0.0f;
    if (i < GG) g_cnt[i] = 0.0f;
}

// one warp / node: pooled[batch[n]] += h[n]; cnt[batch[n]] += 1
__global__ void pool_scatter_kernel(const int* __restrict__ batch, const float* __restrict__ h) {
    const int n = (blockIdx.x * blockDim.x + threadIdx.x) >> 5;
    const int lane = threadIdx.x & 31;
    if (n >= NN) return;
    const int g = batch[n];
    float4 v = *(const float4*)(h + (size_t)n * HH + (lane << 2));
    float* p = g_pool + (size_t)g * HH + (lane << 2);
    asm volatile("red.global.add.v4.f32 [%0], {%1,%2,%3,%4};"
                 :: "l"(p), "f"(v.x), "f"(v.y), "f"(v.z), "f"(v.w)
                 : "memory");
    if (lane == 0) atomicAdd(&g_cnt[g], 1.0f);
}

// ---------------------------------------------------------------------------
extern "C" void kernel_launch(void* const* d_in, const int* in_sizes, int n_in,
                              void* d_out, int out_size) {
    const int*   x     = (const int*)d_in[0];
    const int*   ei    = (const int*)d_in[1];
    const int*   batch = (const int*)d_in[2];
    const float* emb   = (const float*)d_in[3];
    const float* W1    = (const float*)d_in[4];
    const float* b1    = (const float*)d_in[5];
    const float* W2    = (const float*)d_in[6];
    const float* b2    = (const float*)d_in[7];
    const float* W3    = (const float*)d_in[8];
    const float* b3    = (const float*)d_in[9];
    const float* Wl    = (const float*)d_in[10];
    const float* bl    = (const float*)d_in[11];
    float* out = (float*)d_out;

    const int* srcp = ei;
    const int* dstp = ei + EE;

    float *p_h, *p_t, *p_o, *p_pool;
    cudaGetSymbolAddress((void**)&p_h, g_h);
    cudaGetSymbolAddress((void**)&p_t, g_t);
    cudaGetSymbolAddress((void**)&p_o, g_o);
    cudaGetSymbolAddress((void**)&p_pool, g_pool);

    // degree (with self-loop) -> dinv
    deg_init_kernel<<<(NN + 255) / 256, 256>>>();
    deg_scatter_kernel<<<(EE + 255) / 256, 256>>>(dstp);

    // atom embedding sum + dinv conversion
    embed_kernel<<<NN, 128>>>(x, emb);

    const int gemm_blocks = (NN + 127) / 128;
    const int edge_blocks = (EE * 32 + 255) / 256;

    // Layer 1: h -> t; o = dinv^2*t + b1; scatter into o
    gemm_kernel<0><<<gemm_blocks, 256>>>(p_h, W1, b1, p_t, p_o, NN);
    edge_kernel<<<edge_blocks, 256>>>(srcp, dstp, p_t, p_o);

    // Layer 2: relu(o) -> t; h = dinv^2*t + b2; scatter into h
    gemm_kernel<1><<<gemm_blocks, 256>>>(p_o, W2, b2, p_t, p_h, NN);
    edge_kernel<<<edge_blocks, 256>>>(srcp, dstp, p_t, p_h);

    // Layer 3: relu(h) -> t; o = dinv^2*t + b3; scatter into o
    gemm_kernel<1><<<gemm_blocks, 256>>>(p_h, W3, b3, p_t, p_o, NN);
    edge_kernel<<<edge_blocks, 256>>>(srcp, dstp, p_t, p_o);

    // Mean pool + final linear
    pool_zero_kernel<<<(GG * HH + 255) / 256, 256>>>();
    pool_scatter_kernel<<<(NN * 32 + 255) / 256, 256>>>(batch, p_o);
    gemm_kernel<2><<<(GG + 127) / 128, 256>>>(p_pool, Wl, bl, nullptr, out, GG);
}

// round 8
// speedup vs baseline: 1.4097x; 1.4097x over previous
#include <cuda_runtime.h>
#include <cuda_bf16.h>

// Problem constants (fixed shapes per reference)
#define NN 100000
#define EE 600000
#define HH 128
#define GG 4000
#define TT 128

// Scratch (allocation-free: device globals)
__device__ float g_deg[NN];                 // degree, then dinv in-place
__device__ float g_h[(size_t)NN * HH];
__device__ float g_t[(size_t)NN * HH];
__device__ float g_o[(size_t)NN * HH];
__device__ float g_pool[(size_t)GG * HH];
__device__ float g_cnt[GG];

__constant__ int c_off[9] = {0, 119, 124, 136, 148, 158, 164, 170, 172};

// ---------------------------------------------------------------------------
__global__ void deg_init_kernel() {
    int i = blockIdx.x * blockDim.x + threadIdx.x;
    if (i < NN) g_deg[i] = 1.0f;
}

__global__ void deg_scatter_kernel(const int* __restrict__ dst) {
    int e = blockIdx.x * blockDim.x + threadIdx.x;
    if (e < EE) atomicAdd(&g_deg[dst[e]], 1.0f);
}

// AtomEncoder: h[n] = sum_f emb[x[n,f]+off[f]]; also deg -> dinv in place.
__global__ void embed_kernel(const int* __restrict__ x, const float* __restrict__ emb) {
    int n = blockIdx.x;
    int t = threadIdx.x;
    __shared__ int xi[9];
    if (t < 9) xi[t] = x[n * 9 + t] + c_off[t];
    __syncthreads();
    float v = 0.0f;
#pragma unroll
    for (int f = 0; f < 9; f++) v += emb[(size_t)xi[f] * HH + t];
    g_h[(size_t)n * HH + t] = v;
    if (t == 0) g_deg[n] = rsqrtf(g_deg[n]);
}

// ---------------------------------------------------------------------------
// GEMM: C[M,128] = A'[M,128] @ B[128,128]
// MODE 0: layer, A as-is.  MODE 1: layer, relu(A).  MODE 2: final, A/max(cnt,1).
// Layer epilogue: T = A'@B ; OUT = dinv^2 * T + bias   (self-loop init)
// Final epilogue: OUT = A'@B + bias
//
// Whole A tile (128x128) and whole B (128x128) resident in 128KB dynamic smem.
// Single __syncthreads; inner loop uses packed fma.rn.f32x2 (2 MACs/lane/instr,
// bit-identical rounding to scalar FFMA).
template <int MODE>
__global__ void __launch_bounds__(256, 1)
gemm_kernel(const float* __restrict__ A, const float* __restrict__ B,
            const float* __restrict__ bias, float* __restrict__ T,
            float* __restrict__ OUT, int M) {
    extern __shared__ float sm[];
    float* Bs = sm;             // [k][col], 128x128
    float* As = sm + 16384;     // [row][k], 128x128 (row-major like global)

    const int tid = threadIdx.x;            // 256 threads
    const int row0 = blockIdx.x * 128;

    // Stage B: coalesced, conflict-free.
#pragma unroll
    for (int i = tid; i < 4096; i += 256) {
        const int r = i >> 5, c = (i & 31) << 2;
        *(float4*)&Bs[r * 128 + c] = *(const float4*)&B[r * 128 + c];
    }
    // Stage A (row-major) with MODE transform fused.
#pragma unroll
    for (int i = tid; i < 4096; i += 256) {
        const int r = i >> 5, c = (i & 31) << 2;
        const int gr = row0 + r;
        float4 v = make_float4(0.f, 0.f, 0.f, 0.f);
        if (gr < M) v = *(const float4*)&A[(size_t)gr * HH + c];
        if (MODE == 1) {
            v.x = fmaxf(v.x, 0.f); v.y = fmaxf(v.y, 0.f);
            v.z = fmaxf(v.z, 0.f); v.w = fmaxf(v.w, 0.f);
        }
        if (MODE == 2) {
            const float ps = (gr < M) ? 1.0f / fmaxf(g_cnt[gr], 1.0f) : 0.0f;
            v.x *= ps; v.y *= ps; v.z *= ps; v.w *= ps;
        }
        *(float4*)&As[r * 128 + c] = v;
    }
    __syncthreads();

    const int tx = tid & 15;                 // 16 col groups
    const int ty = tid >> 4;                 // 16 row groups
    const int c0 = tx << 3;                  // 8 cols / thread
    const int r0t = ty << 3;                 // 8 rows / thread

    unsigned long long acc[8][4];            // 8 rows x 4 packed f32x2 col-pairs
#pragma unroll
    for (int i = 0; i < 8; i++)
#pragma unroll
        for (int j = 0; j < 4; j++) acc[i][j] = 0ull;

#pragma unroll 4
    for (int k = 0; k < 128; k++) {
        // B fragment: 8 cols = 4 packed pairs (little-endian: low half = even col)
        const ulonglong2 b01 = *(const ulonglong2*)&Bs[k * 128 + c0];
        const ulonglong2 b23 = *(const ulonglong2*)&Bs[k * 128 + c0 + 4];
        unsigned long long bb[4];
        bb[0] = b01.x; bb[1] = b01.y; bb[2] = b23.x; bb[3] = b23.y;
#pragma unroll
        for (int i = 0; i < 8; i++) {
            const float a = As[(r0t + i) * 128 + k];   // 16-lane broadcast LDS
            unsigned long long a2;
            asm("mov.b64 %0, {%1, %1};" : "=l"(a2) : "f"(a));
#pragma unroll
            for (int j = 0; j < 4; j++)
                asm("fma.rn.f32x2 %0, %1, %2, %0;" : "+l"(acc[i][j]) : "l"(a2), "l"(bb[j]));
        }
    }

    // bias fragment
    float bsv[8];
    {
        const float4 bl0 = *(const float4*)&bias[c0];
        const float4 bl1 = *(const float4*)&bias[c0 + 4];
        bsv[0] = bl0.x; bsv[1] = bl0.y; bsv[2] = bl0.z; bsv[3] = bl0.w;
        bsv[4] = bl1.x; bsv[5] = bl1.y; bsv[6] = bl1.z; bsv[7] = bl1.w;
    }

#pragma unroll
    for (int i = 0; i < 8; i++) {
        const int r = row0 + r0t + i;
        if (r >= M) continue;
        float v[8];
#pragma unroll
        for (int j = 0; j < 4; j++)
            asm("mov.b64 {%0, %1}, %2;" : "=f"(v[2 * j]), "=f"(v[2 * j + 1]) : "l"(acc[i][j]));
        if (MODE == 2) {
            float4 o0, o1;
            o0.x = v[0] + bsv[0]; o0.y = v[1] + bsv[1]; o0.z = v[2] + bsv[2]; o0.w = v[3] + bsv[3];
            o1.x = v[4] + bsv[4]; o1.y = v[5] + bsv[5]; o1.z = v[6] + bsv[6]; o1.w = v[7] + bsv[7];
            *(float4*)&OUT[(size_t)r * TT + c0] = o0;
            *(float4*)&OUT[(size_t)r * TT + c0 + 4] = o1;
        } else {
            const float d = g_deg[r];   // dinv
            const float d2 = d * d;
            float4 t0, t1, o0, o1;
            t0.x = v[0]; t0.y = v[1]; t0.z = v[2]; t0.w = v[3];
            t1.x = v[4]; t1.y = v[5]; t1.z = v[6]; t1.w = v[7];
            o0.x = fmaf(d2, v[0], bsv[0]); o0.y = fmaf(d2, v[1], bsv[1]);
            o0.z = fmaf(d2, v[2], bsv[2]); o0.w = fmaf(d2, v[3], bsv[3]);
            o1.x = fmaf(d2, v[4], bsv[4]); o1.y = fmaf(d2, v[5], bsv[5]);
            o1.z = fmaf(d2, v[6], bsv[6]); o1.w = fmaf(d2, v[7], bsv[7]);
            *(float4*)&T[(size_t)r * HH + c0] = t0;
            *(float4*)&T[(size_t)r * HH + c0 + 4] = t1;
            *(float4*)&OUT[(size_t)r * HH + c0] = o0;
            *(float4*)&OUT[(size_t)r * HH + c0 + 4] = o1;
        }
    }
}

// ---------------------------------------------------------------------------
// Edge scatter: out[dst] += t[src] * dinv[src] * dinv[dst]   (one warp / edge)
__global__ void edge_kernel(const int* __restrict__ src, const int* __restrict__ dst,
                            const float* __restrict__ t, float* __restrict__ out) {
    const int w = (blockIdx.x * blockDim.x + threadIdx.x) >> 5;
    const int lane = threadIdx.x & 31;
    if (w >= EE) return;
    const int s = src[w];
    const int d = dst[w];
    const float c = g_deg[s] * g_deg[d];
    float4 v = *(const float4*)(t + (size_t)s * HH + (lane << 2));
    v.x *= c; v.y *= c; v.z *= c; v.w *= c;
    float* p = out + (size_t)d * HH + (lane << 2);
    asm volatile("red.global.add.v4.f32 [%0], {%1,%2,%3,%4};"
                 :: "l"(p), "f"(v.x), "f"(v.y), "f"(v.z), "f"(v.w)
                 : "memory");
}

// ---------------------------------------------------------------------------
__global__ void pool_zero_kernel() {
    int i = blockIdx.x * blockDim.x + threadIdx.x;
    if (i < GG * HH) g_pool[i] = 0.0f;
    if (i < GG) g_cnt[i] = 0.0f;
}

// one warp / node: pooled[batch[n]] += h[n]; cnt[batch[n]] += 1
__global__ void pool_scatter_kernel(const int* __restrict__ batch, const float* __restrict__ h) {
    const int n = (blockIdx.x * blockDim.x + threadIdx.x) >> 5;
    const int lane = threadIdx.x & 31;
    if (n >= NN) return;
    const int g = batch[n];
    float4 v = *(const float4*)(h + (size_t)n * HH + (lane << 2));
    float* p = g_pool + (size_t)g * HH + (lane << 2);
    asm volatile("red.global.add.v4.f32 [%0], {%1,%2,%3,%4};"
                 :: "l"(p), "f"(v.x), "f"(v.y), "f"(v.z), "f"(v.w)
                 : "memory");
    if (lane == 0) atomicAdd(&g_cnt[g], 1.0f);
}

// ---------------------------------------------------------------------------
extern "C" void kernel_launch(void* const* d_in, const int* in_sizes, int n_in,
                              void* d_out, int out_size) {
    const int*   x     = (const int*)d_in[0];
    const int*   ei    = (const int*)d_in[1];
    const int*   batch = (const int*)d_in[2];
    const float* emb   = (const float*)d_in[3];
    const float* W1    = (const float*)d_in[4];
    const float* b1    = (const float*)d_in[5];
    const float* W2    = (const float*)d_in[6];
    const float* b2    = (const float*)d_in[7];
    const float* W3    = (const float*)d_in[8];
    const float* b3    = (const float*)d_in[9];
    const float* Wl    = (const float*)d_in[10];
    const float* bl    = (const float*)d_in[11];
    float* out = (float*)d_out;

    const int* srcp = ei;
    const int* dstp = ei + EE;

    float *p_h, *p_t, *p_o, *p_pool;
    cudaGetSymbolAddress((void**)&p_h, g_h);
    cudaGetSymbolAddress((void**)&p_t, g_t);
    cudaGetSymbolAddress((void**)&p_o, g_o);
    cudaGetSymbolAddress((void**)&p_pool, g_pool);

    const int SMEM = 2 * 128 * 128 * (int)sizeof(float);   // 128KB dynamic smem
    static bool attr_set = false;
    if (!attr_set) {
        cudaFuncSetAttribute(gemm_kernel<0>, cudaFuncAttributeMaxDynamicSharedMemorySize, SMEM);
        cudaFuncSetAttribute(gemm_kernel<1>, cudaFuncAttributeMaxDynamicSharedMemorySize, SMEM);
        cudaFuncSetAttribute(gemm_kernel<2>, cudaFuncAttributeMaxDynamicSharedMemorySize, SMEM);
        attr_set = true;
    }

    // degree (with self-loop) -> dinv
    deg_init_kernel<<<(NN + 255) / 256, 256>>>();
    deg_scatter_kernel<<<(EE + 255) / 256, 256>>>(dstp);

    // atom embedding sum + dinv conversion
    embed_kernel<<<NN, 128>>>(x, emb);

    const int gemm_blocks = (NN + 127) / 128;
    const int edge_blocks = (EE * 32 + 255) / 256;

    // Layer 1: h -> t; o = dinv^2*t + b1; scatter into o
    gemm_kernel<0><<<gemm_blocks, 256, SMEM>>>(p_h, W1, b1, p_t, p_o, NN);
    edge_kernel<<<edge_blocks, 256>>>(srcp, dstp, p_t, p_o);

    // Layer 2: relu(o) -> t; h = dinv^2*t + b2; scatter into h
    gemm_kernel<1><<<gemm_blocks, 256, SMEM>>>(p_o, W2, b2, p_t, p_h, NN);
    edge_kernel<<<edge_blocks, 256>>>(srcp, dstp, p_t, p_h);

    // Layer 3: relu(h) -> t; o = dinv^2*t + b3; scatter into o
    gemm_kernel<1><<<gemm_blocks, 256, SMEM>>>(p_h, W3, b3, p_t, p_o, NN);
    edge_kernel<<<edge_blocks, 256>>>(srcp, dstp, p_t, p_o);

    // Mean pool + final linear
    pool_zero_kernel<<<(GG * HH + 255) / 256, 256>>>();
    pool_scatter_kernel<<<(NN * 32 + 255) / 256, 256>>>(batch, p_o);
    gemm_kernel<2><<<(GG + 127) / 128, 256, SMEM>>>(p_pool, Wl, bl, nullptr, out, GG);
}